// round 10
// baseline (speedup 1.0000x reference)
#include <cuda_runtime.h>
#include <cstdint>

#define E_DIM 128
#define B_SZ  1024
#define T_SZ  200
#define NTHR  256

#define ROW_A 272
#define ROW_B 272

#define OFF_A    0           // 208*272 = 56576
#define OFF_B    56576       // 64*272  = 17408
#define OFF_QAP  73984       // 4*64 f32 = 1024 (qA partials)
#define OFF_RED  75008       // 2*208 f32 = 1664
#define SMEM_BYTES 76736

// folded weights (device scratch; written by prep0, read via L2 by all CTAs)
__device__ float g_Wk[64 * 128];   // [h*128+e]  W0b - W0c
__device__ float g_Wd[64 * 128];   // [h*128+e]  W0d
__device__ float g_Wq[64 * 128];   // [h*128+e]  W0a + W0c

__device__ __forceinline__ uint32_t pkf16(float lo, float hi) {
    uint32_t r;
    asm("cvt.rn.f16x2.f32 %0, %1, %2;" : "=r"(r) : "f"(hi), "f"(lo));
    return r;
}
__device__ __forceinline__ uint32_t smem_u32(const void* p) {
    uint32_t a;
    asm("{ .reg .u64 t; cvta.to.shared.u64 t, %1; cvt.u32.u64 %0, t; }" : "=r"(a) : "l"(p));
    return a;
}

#define LDSM4(r, addr) \
    asm volatile("ldmatrix.sync.aligned.m8n8.x4.shared.b16 {%0,%1,%2,%3}, [%4];" \
        : "=r"((r)[0]), "=r"((r)[1]), "=r"((r)[2]), "=r"((r)[3]) : "r"(addr))

__device__ __forceinline__ void mma_f16(float* c, const uint32_t* a, uint32_t b0, uint32_t b1) {
    asm volatile("mma.sync.aligned.m16n8k16.row.col.f32.f16.f16.f32 "
        "{%0,%1,%2,%3}, {%4,%5,%6,%7}, {%8,%9}, {%0,%1,%2,%3};"
        : "+f"(c[0]), "+f"(c[1]), "+f"(c[2]), "+f"(c[3])
        : "r"(a[0]), "r"(a[1]), "r"(a[2]), "r"(a[3]), "r"(b0), "r"(b1));
}

// fold W0 [512,64] once
__global__ void prep0(const float* __restrict__ W0) {
    int idx = blockIdx.x * blockDim.x + threadIdx.x;   // 8192
    int e = idx & 127, h = idx >> 7;
    float wa = W0[e * 64 + h];
    float wb = W0[(128 + e) * 64 + h];
    float wc = W0[(256 + e) * 64 + h];
    float wd = W0[(384 + e) * 64 + h];
    g_Wk[h * 128 + e] = wb - wc;
    g_Wd[h * 128 + e] = wd;
    g_Wq[h * 128 + e] = wa + wc;
}

// one batch per CTA; 2 CTAs per SM overlap phases
__global__ void __launch_bounds__(NTHR, 2) lau_main(
    const float* __restrict__ keys, const float* __restrict__ query,
    const float* __restrict__ b0,   const float* __restrict__ W1,
    const float* __restrict__ b1,   float* __restrict__ out)
{
    extern __shared__ __align__(1024) char sm[];
    const uint32_t smb = smem_u32(sm);
    const int tid = threadIdx.x;
    const int b = blockIdx.x;
    const int w = tid >> 5, lane = tid & 31;
    const int mg = w >> 1, ng = w & 1;          // 4 m-groups x 2 n-groups
    const int lq = lane >> 2, lr = lane & 3;

    float* sQAP = (float*)(sm + OFF_QAP);
    float* sRed = (float*)(sm + OFF_RED);
    const float* qb = query + (size_t)b * E_DIM;

    // ---- build B = W_b(b) = Wk + diag(q_b)·Wd  (fp16, ldmatrix layout) ----
    {
        const int bh = tid >> 2, be = (tid & 3) * 32;
        const float4* wk4 = (const float4*)(g_Wk + bh * 128 + be);
        const float4* wd4 = (const float4*)(g_Wd + bh * 128 + be);
        const float4* q4  = (const float4*)(qb + be);
        #pragma unroll
        for (int i = 0; i < 4; i++) {
            float4 k0 = __ldg(&wk4[2 * i]),     k1 = __ldg(&wk4[2 * i + 1]);
            float4 d0 = __ldg(&wd4[2 * i]),     d1 = __ldg(&wd4[2 * i + 1]);
            float4 q0 = __ldg(&q4[2 * i]),      q1 = __ldg(&q4[2 * i + 1]);
            uint4 pk;
            pk.x = pkf16(fmaf(q0.x, d0.x, k0.x), fmaf(q0.y, d0.y, k0.y));
            pk.y = pkf16(fmaf(q0.z, d0.z, k0.z), fmaf(q0.w, d0.w, k0.w));
            pk.z = pkf16(fmaf(q1.x, d1.x, k1.x), fmaf(q1.y, d1.y, k1.y));
            pk.w = pkf16(fmaf(q1.z, d1.z, k1.z), fmaf(q1.w, d1.w, k1.w));
            *(uint4*)(sm + OFF_B + bh * ROW_B + (be + i * 8) * 2) = pk;
        }
    }

    // ---- qA partials: p[grp][h] = sum_{e in grp} q[e]*Wq[e,h] ----
    {
        const int h6 = tid & 63, grp = tid >> 6;
        const float4* wq4 = (const float4*)(g_Wq + h6 * 128 + grp * 32);
        const float4* q4  = (const float4*)(qb + grp * 32);
        float p = 0.f;
        #pragma unroll
        for (int i = 0; i < 8; i++) {
            float4 wv = __ldg(&wq4[i]);
            float4 qv = __ldg(&q4[i]);
            p += wv.x * qv.x + wv.y * qv.y + wv.z * qv.z + wv.w * qv.w;
        }
        sQAP[grp * 64 + h6] = p;
    }

    // ---- zero A tail rows 200-207 ----
    if (tid < 136)
        *(uint4*)(sm + OFF_A + 200 * ROW_A + tid * 16) = make_uint4(0, 0, 0, 0);

    // ---- keys -> fp16 A (LDG.128 x2 -> cvt -> STS.128) ----
    {
        const float4* k4 = (const float4*)(keys + (size_t)b * T_SZ * E_DIM);
        #pragma unroll
        for (int i = 0; i < 13; i++) {
            int g = i * NTHR + tid;              // 8-float group, 3200 total
            if (g < 3200) {
                int row = g >> 4, c16 = g & 15;
                float4 v0 = __ldg(&k4[2 * g]);
                float4 v1 = __ldg(&k4[2 * g + 1]);
                uint4 pk;
                pk.x = pkf16(v0.x, v0.y);
                pk.y = pkf16(v0.z, v0.w);
                pk.z = pkf16(v1.x, v1.y);
                pk.w = pkf16(v1.z, v1.w);
                *(uint4*)(sm + OFF_A + row * ROW_A + c16 * 16) = pk;
            }
        }
    }
    __syncthreads();                              // (1) A, B, qA partials ready

    // ---- per-thread epilogue constants (8 cols) ----
    float qa[8], w1v[8];
    {
        #pragma unroll
        for (int nt = 0; nt < 4; nt++) {
            #pragma unroll
            for (int u = 0; u < 2; u++) {
                int c = ng * 32 + nt * 8 + 2 * lr + u;
                qa[2 * nt + u] = __ldg(&b0[c]) + sQAP[c] + sQAP[64 + c]
                               + sQAP[128 + c] + sQAP[192 + c];
                w1v[2 * nt + u] = __ldg(&W1[c]);
            }
        }
    }

    // ---- B fragments to registers (held whole batch) ----
    const uint32_t bB = smb + OFF_B + (ng * 32 + (lane & 7)) * ROW_B + ((lane >> 3) & 3) * 16;
    uint32_t bf[4][8][2];
    #pragma unroll
    for (int nt = 0; nt < 4; nt++)
        #pragma unroll
        for (int k2 = 0; k2 < 4; k2++) {
            uint32_t t[4];
            LDSM4(t, bB + nt * (8 * ROW_B) + k2 * 64);
            bf[nt][2 * k2][0] = t[0];     bf[nt][2 * k2][1] = t[1];
            bf[nt][2 * k2 + 1][0] = t[2]; bf[nt][2 * k2 + 1][1] = t[3];
        }

    // ---- per-tile: ldsm A, mma, inline epilogue ----
    const uint32_t aB = smb + OFF_A + (lane & 15) * ROW_A + (lane >> 4) * 16;
    #pragma unroll
    for (int i = 0; i < 4; i++) {
        int t = mg + 4 * i;
        if (t < 13) {
            float acc[4][4];
            #pragma unroll
            for (int nt = 0; nt < 4; nt++)
                #pragma unroll
                for (int u = 0; u < 4; u++) acc[nt][u] = 0.f;
            #pragma unroll
            for (int ks = 0; ks < 8; ks++) {
                uint32_t a[4];
                LDSM4(a, aB + t * (16 * ROW_A) + ks * 32);
                #pragma unroll
                for (int nt = 0; nt < 4; nt++)
                    mma_f16(acc[nt], a, bf[nt][ks][0], bf[nt][ks][1]);
            }
            float p0 = 0.f, p1 = 0.f;
            #pragma unroll
            for (int nt = 0; nt < 4; nt++) {
                p0 += fmaxf(acc[nt][0] + qa[2 * nt],     0.f) * w1v[2 * nt]
                    + fmaxf(acc[nt][1] + qa[2 * nt + 1], 0.f) * w1v[2 * nt + 1];
                p1 += fmaxf(acc[nt][2] + qa[2 * nt],     0.f) * w1v[2 * nt]
                    + fmaxf(acc[nt][3] + qa[2 * nt + 1], 0.f) * w1v[2 * nt + 1];
            }
            p0 += __shfl_xor_sync(0xffffffffu, p0, 1);
            p0 += __shfl_xor_sync(0xffffffffu, p0, 2);
            p1 += __shfl_xor_sync(0xffffffffu, p1, 1);
            p1 += __shfl_xor_sync(0xffffffffu, p1, 2);
            if (lr == 0) {
                sRed[ng * 208 + t * 16 + lq]     = p0;
                sRed[ng * 208 + t * 16 + lq + 8] = p1;
            }
        }
    }
    __syncthreads();                              // (2)
    if (tid < T_SZ)
        out[(size_t)b * T_SZ + tid] = sRed[tid] + sRed[208 + tid] + __ldg(b1);
}

extern "C" void kernel_launch(void* const* d_in, const int* in_sizes, int n_in,
                              void* d_out, int out_size) {
    const float* query = (const float*)d_in[0];
    const float* keys  = (const float*)d_in[1];
    const float* W0    = (const float*)d_in[2];
    const float* b0    = (const float*)d_in[3];
    const float* W1    = (const float*)d_in[4];
    const float* b1    = (const float*)d_in[5];
    float* out = (float*)d_out;

    cudaFuncSetAttribute(lau_main, cudaFuncAttributeMaxDynamicSharedMemorySize, SMEM_BYTES);

    prep0<<<32, 256>>>(W0);
    lau_main<<<B_SZ, NTHR, SMEM_BYTES>>>(keys, query, b0, W1, b1, out);
}

// round 11
// speedup vs baseline: 1.0806x; 1.0806x over previous
#include <cuda_runtime.h>
#include <cstdint>

#define E_DIM 128
#define B_SZ  1024
#define T_SZ  200
#define GRID  148
#define NTHR  512

#define ROW_A 272            // 128 fp16 padded to 272B (ldmatrix conflict-free)
#define ROW_B 272
#define ROW_W 132            // fp32 row stride (528B, 16B-aligned)

#define OFF_A0   0           // 208*272 = 56576
#define OFF_A1   56576
#define OFF_B0   113152      // 64*272 = 17408
#define OFF_B1   130560
#define OFF_WK   147968      // 64*132*4 = 33792
#define OFF_WD   181760      // 33792
#define OFF_QAP  215552      // 2 x 256 f32 = 2048
#define OFF_RED  217600      // 2 x 416 f32 = 3328
#define SMEM_BYTES 220928

// barrier ids: 1,2 = FULL(p), 3,4 = FREE(p), 5 = consumer-internal
#define BAR_SYNC(id, cnt)   asm volatile("bar.sync %0, %1;"   :: "r"(id), "r"(cnt) : "memory")
#define BAR_ARRIVE(id, cnt) asm volatile("bar.arrive %0, %1;" :: "r"(id), "r"(cnt) : "memory")

__device__ __forceinline__ uint32_t pkf16(float lo, float hi) {
    uint32_t r;
    asm("cvt.rn.f16x2.f32 %0, %1, %2;" : "=r"(r) : "f"(hi), "f"(lo));
    return r;
}
__device__ __forceinline__ uint32_t smem_u32(const void* p) {
    uint32_t a;
    asm("{ .reg .u64 t; cvta.to.shared.u64 t, %1; cvt.u32.u64 %0, t; }" : "=r"(a) : "l"(p));
    return a;
}

#define LDSM4(r, addr) \
    asm volatile("ldmatrix.sync.aligned.m8n8.x4.shared.b16 {%0,%1,%2,%3}, [%4];" \
        : "=r"((r)[0]), "=r"((r)[1]), "=r"((r)[2]), "=r"((r)[3]) : "r"(addr))

__device__ __forceinline__ void mma_f16(float* c, const uint32_t* a, uint32_t b0, uint32_t b1) {
    asm volatile("mma.sync.aligned.m16n8k16.row.col.f32.f16.f16.f32 "
        "{%0,%1,%2,%3}, {%4,%5,%6,%7}, {%8,%9}, {%0,%1,%2,%3};"
        : "+f"(c[0]), "+f"(c[1]), "+f"(c[2]), "+f"(c[3])
        : "r"(a[0]), "r"(a[1]), "r"(a[2]), "r"(a[3]), "r"(b0), "r"(b1));
}

__global__ void __launch_bounds__(NTHR, 1) lau_main(
    const float* __restrict__ keys, const float* __restrict__ query,
    const float* __restrict__ W0,   const float* __restrict__ b0,
    const float* __restrict__ W1,   const float* __restrict__ b1,
    float* __restrict__ out)
{
    extern __shared__ __align__(1024) char sm[];
    const uint32_t smb = smem_u32(sm);
    const int tid = threadIdx.x;
    const int bid = blockIdx.x;

    float* sWk = (float*)(sm + OFF_WK);
    float* sWd = (float*)(sm + OFF_WD);

    // ---- prologue (all 512 threads): fold W0 -> smem, zero A tails ----
    for (int idx = tid; idx < 8192; idx += NTHR) {
        int h = idx & 63, e = idx >> 6;
        float wb = __ldg(&W0[(128 + e) * 64 + h]);
        float wc = __ldg(&W0[(256 + e) * 64 + h]);
        float wd = __ldg(&W0[(384 + e) * 64 + h]);
        sWk[h * ROW_W + e] = wb - wc;
        sWd[h * ROW_W + e] = wd;
    }
    for (int i = tid; i < 272; i += NTHR) {
        int buf = (i < 136) ? OFF_A0 : OFF_A1;
        *(uint4*)(sm + buf + 200 * ROW_A + (i % 136) * 16) = make_uint4(0, 0, 0, 0);
    }
    const float b1v = __ldg(b1);
    __syncthreads();

    if (tid < 256) {
        // ================= PRODUCER (warps 0-7) =================
        const int bh = tid >> 2, be = (tid & 3) * 32;       // W_b build
        const int h6 = tid & 63, grp = tid >> 6;            // qA partials
        int j = 0;
        for (int b = bid; b < B_SZ; b += GRID, j++) {
            const int p = j & 1;
            if (j >= 2) BAR_SYNC(3 + p, NTHR);              // wait buf p free
            const uint32_t offA = p ? OFF_A1 : OFF_A0;
            const uint32_t offB = p ? OFF_B1 : OFF_B0;
            const float* qb = query + (size_t)b * E_DIM;
            const float4* q4 = (const float4*)qb;

            // A: keys -> fp16 (LDG.128 -> cvt -> STS.64)
            const float4* k4 = (const float4*)(keys + (size_t)b * T_SZ * E_DIM);
            #pragma unroll
            for (int i = 0; i < 25; i++) {
                int idx = i * 256 + tid;                    // 6400 float4
                int row = idx >> 5, cc = idx & 31;
                float4 v = __ldg(&k4[idx]);
                *(uint2*)(sm + offA + row * ROW_A + cc * 8) =
                    make_uint2(pkf16(v.x, v.y), pkf16(v.z, v.w));
            }

            // B: W_b = Wk + diag(q_b)·Wd  (fp16, ldmatrix layout)
            #pragma unroll
            for (int i = 0; i < 4; i++) {
                int e0 = be + i * 8;
                float4 k0 = *(const float4*)(sWk + bh * ROW_W + e0);
                float4 k1 = *(const float4*)(sWk + bh * ROW_W + e0 + 4);
                float4 d0 = *(const float4*)(sWd + bh * ROW_W + e0);
                float4 d1 = *(const float4*)(sWd + bh * ROW_W + e0 + 4);
                float4 q0 = __ldg(&q4[e0 >> 2]);
                float4 q1 = __ldg(&q4[(e0 >> 2) + 1]);
                uint4 pk;
                pk.x = pkf16(fmaf(q0.x, d0.x, k0.x), fmaf(q0.y, d0.y, k0.y));
                pk.y = pkf16(fmaf(q0.z, d0.z, k0.z), fmaf(q0.w, d0.w, k0.w));
                pk.z = pkf16(fmaf(q1.x, d1.x, k1.x), fmaf(q1.y, d1.y, k1.y));
                pk.w = pkf16(fmaf(q1.z, d1.z, k1.z), fmaf(q1.w, d1.w, k1.w));
                *(uint4*)(sm + offB + bh * ROW_B + e0 * 2) = pk;
            }

            // qA partials: p[grp][h] = sum_{e in grp*32..} q[e]*(W0a+W0c)[e,h]
            {
                float pp = 0.f;
                #pragma unroll
                for (int i4 = 0; i4 < 8; i4++) {
                    int e = grp * 32 + i4 * 4;
                    float4 qv = __ldg(&q4[e >> 2]);
                    pp += qv.x * (__ldg(&W0[e * 64 + h6])       + __ldg(&W0[(256 + e) * 64 + h6]));
                    pp += qv.y * (__ldg(&W0[(e + 1) * 64 + h6]) + __ldg(&W0[(257 + e) * 64 + h6]));
                    pp += qv.z * (__ldg(&W0[(e + 2) * 64 + h6]) + __ldg(&W0[(258 + e) * 64 + h6]));
                    pp += qv.w * (__ldg(&W0[(e + 3) * 64 + h6]) + __ldg(&W0[(259 + e) * 64 + h6]));
                }
                ((float*)(sm + OFF_QAP + p * 1024))[grp * 64 + h6] = pp;
            }

            asm volatile("membar.cta;" ::: "memory");
            BAR_ARRIVE(1 + p, NTHR);                        // buf p full
        }
    } else {
        // ================= CONSUMER (warps 8-15) =================
        const int ct = tid - 256;
        const int w = ct >> 5, lane = ct & 31;
        const int mg = w >> 1, ng = w & 1;                  // 4 m-groups x 2 n-groups
        const int lq = lane >> 2, lr = lane & 3;

        float w1v[8];
        #pragma unroll
        for (int nt = 0; nt < 4; nt++) {
            w1v[2 * nt]     = __ldg(&W1[ng * 32 + nt * 8 + 2 * lr]);
            w1v[2 * nt + 1] = __ldg(&W1[ng * 32 + nt * 8 + 2 * lr + 1]);
        }

        int j = 0;
        for (int b = bid; b < B_SZ; b += GRID, j++) {
            const int p = j & 1;
            BAR_SYNC(1 + p, NTHR);                          // wait buf p full
            const uint32_t offA = p ? OFF_A1 : OFF_A0;
            const uint32_t offB = p ? OFF_B1 : OFF_B0;
            float* qap  = (float*)(sm + OFF_QAP + p * 1024);
            float* sRed = (float*)(sm + OFF_RED + p * 1664);

            // per-thread qa for this batch's 8 columns
            float qa[8];
            #pragma unroll
            for (int nt = 0; nt < 4; nt++) {
                #pragma unroll
                for (int u = 0; u < 2; u++) {
                    int c = ng * 32 + nt * 8 + 2 * lr + u;
                    qa[2 * nt + u] = __ldg(&b0[c]) + qap[c] + qap[64 + c]
                                   + qap[128 + c] + qap[192 + c];
                }
            }

            // B fragments (whole batch in regs)
            const uint32_t bB = smb + offB + (ng * 32 + (lane & 7)) * ROW_B
                              + ((lane >> 3) & 3) * 16;
            uint32_t bf[4][8][2];
            #pragma unroll
            for (int nt = 0; nt < 4; nt++)
                #pragma unroll
                for (int k2 = 0; k2 < 4; k2++) {
                    uint32_t t[4];
                    LDSM4(t, bB + nt * (8 * ROW_B) + k2 * 64);
                    bf[nt][2 * k2][0] = t[0];     bf[nt][2 * k2][1] = t[1];
                    bf[nt][2 * k2 + 1][0] = t[2]; bf[nt][2 * k2 + 1][1] = t[3];
                }

            // per-tile mma + inline epilogue
            const uint32_t aB = smb + offA + (lane & 15) * ROW_A + (lane >> 4) * 16;
            #pragma unroll
            for (int i = 0; i < 4; i++) {
                int t = mg + 4 * i;
                if (t < 13) {
                    float acc[4][4];
                    #pragma unroll
                    for (int nt = 0; nt < 4; nt++)
                        #pragma unroll
                        for (int u = 0; u < 4; u++) acc[nt][u] = 0.f;
                    #pragma unroll
                    for (int ks = 0; ks < 8; ks++) {
                        uint32_t a[4];
                        LDSM4(a, aB + t * (16 * ROW_A) + ks * 32);
                        #pragma unroll
                        for (int nt = 0; nt < 4; nt++)
                            mma_f16(acc[nt], a, bf[nt][ks][0], bf[nt][ks][1]);
                    }
                    float p0 = 0.f, p1 = 0.f;
                    #pragma unroll
                    for (int nt = 0; nt < 4; nt++) {
                        p0 += fmaxf(acc[nt][0] + qa[2 * nt],     0.f) * w1v[2 * nt]
                            + fmaxf(acc[nt][1] + qa[2 * nt + 1], 0.f) * w1v[2 * nt + 1];
                        p1 += fmaxf(acc[nt][2] + qa[2 * nt],     0.f) * w1v[2 * nt]
                            + fmaxf(acc[nt][3] + qa[2 * nt + 1], 0.f) * w1v[2 * nt + 1];
                    }
                    p0 += __shfl_xor_sync(0xffffffffu, p0, 1);
                    p0 += __shfl_xor_sync(0xffffffffu, p0, 2);
                    p1 += __shfl_xor_sync(0xffffffffu, p1, 1);
                    p1 += __shfl_xor_sync(0xffffffffu, p1, 2);
                    if (lr == 0) {
                        sRed[ng * 208 + t * 16 + lq]     = p0;
                        sRed[ng * 208 + t * 16 + lq + 8] = p1;
                    }
                }
            }
            BAR_ARRIVE(3 + p, NTHR);                        // buf p free (A/B reads done)
            BAR_SYNC(5, 256);                               // consumer-internal: sRed ready
            if (ct < T_SZ)
                out[(size_t)b * T_SZ + ct] = sRed[ct] + sRed[208 + ct] + b1v;
        }
    }
}

extern "C" void kernel_launch(void* const* d_in, const int* in_sizes, int n_in,
                              void* d_out, int out_size) {
    const float* query = (const float*)d_in[0];
    const float* keys  = (const float*)d_in[1];
    const float* W0    = (const float*)d_in[2];
    const float* b0    = (const float*)d_in[3];
    const float* W1    = (const float*)d_in[4];
    const float* b1    = (const float*)d_in[5];
    float* out = (float*)d_out;

    cudaFuncSetAttribute(lau_main, cudaFuncAttributeMaxDynamicSharedMemorySize, SMEM_BYTES);
    lau_main<<<GRID, NTHR, SMEM_BYTES>>>(keys, query, W0, b0, W1, b1, out);
}